// round 5
// baseline (speedup 1.0000x reference)
#include <cuda_runtime.h>
#include <cuda_bf16.h>
#include <cstdint>
#include <cstddef>

#define N_NODES 50000
#define N_EDGES 600000
#define F 128

// ---------------- scratch (static device globals) ----------------------------
__device__ int   g_deg[N_NODES];
__device__ int   g_start[N_NODES];
__device__ int   g_pos[N_NODES];
__device__ float g_inv[N_NODES];
__device__ int   g_elist[N_EDGES];
__device__ int   g_total;

__device__ __align__(16) __nv_bfloat16 g_a0hi[N_NODES * F];
__device__ __align__(16) __nv_bfloat16 g_a0lo[N_NODES * F];
__device__ __align__(16) __nv_bfloat16 g_a1hi[N_NODES * F];
__device__ __align__(16) __nv_bfloat16 g_a1lo[N_NODES * F];
__device__ __align__(16) __nv_bfloat16 g_a2hi[N_NODES * F];
__device__ __align__(16) __nv_bfloat16 g_a2lo[N_NODES * F];
__device__ __align__(16) __nv_bfloat16 g_wts[12 * F * F];  // per layer: Wshi,Wslo,Wnhi,Wnlo

// ---------------- helpers ----------------------------------------------------
__device__ __forceinline__ uint32_t smem_u32(const void* p) {
    uint32_t a;
    asm("{ .reg .u64 t; cvta.to.shared.u64 t, %1; cvt.u32.u64 %0, t; }" : "=r"(a) : "l"(p));
    return a;
}
__device__ __forceinline__ void cp_async16(uint32_t dst, const void* src, uint32_t pbytes) {
    asm volatile("cp.async.cg.shared.global [%0], [%1], 16, %2;"
                 :: "r"(dst), "l"(src), "r"(pbytes));
}
__device__ __forceinline__ void cp_commit() { asm volatile("cp.async.commit_group;"); }
template <int N>
__device__ __forceinline__ void cp_wait() { asm volatile("cp.async.wait_group %0;" :: "n"(N)); }

__device__ __forceinline__ void ldm_x4(uint32_t* r, uint32_t addr) {
    asm volatile("ldmatrix.sync.aligned.m8n8.x4.shared.b16 {%0,%1,%2,%3}, [%4];"
                 : "=r"(r[0]), "=r"(r[1]), "=r"(r[2]), "=r"(r[3]) : "r"(addr));
}
__device__ __forceinline__ void mma_bf16(float* d, const uint32_t* a, uint32_t b0, uint32_t b1) {
    asm volatile("mma.sync.aligned.m16n8k16.row.col.f32.bf16.bf16.f32 "
                 "{%0,%1,%2,%3}, {%4,%5,%6,%7}, {%8,%9}, {%0,%1,%2,%3};"
                 : "+f"(d[0]), "+f"(d[1]), "+f"(d[2]), "+f"(d[3])
                 : "r"(a[0]), "r"(a[1]), "r"(a[2]), "r"(a[3]), "r"(b0), "r"(b1));
}

// ---------------- CSR build (scan-free) --------------------------------------
__global__ void zero_deg_kernel() {
    int i = blockIdx.x * blockDim.x + threadIdx.x;
    if (i < N_NODES) g_deg[i] = 0;
    if (i == 0) g_total = 0;
}
__global__ void count_deg_kernel(const int* __restrict__ dst) {
    int e = blockIdx.x * blockDim.x + threadIdx.x;
    if (e < N_EDGES) atomicAdd(&g_deg[dst[e]], 1);
}
__global__ void assign_start_kernel() {
    int i = blockIdx.x * blockDim.x + threadIdx.x;
    if (i >= N_NODES) return;
    int d = g_deg[i];
    int s = atomicAdd(&g_total, d);
    g_start[i] = s;
    g_pos[i]   = s;
    g_inv[i]   = 1.0f / fmaxf((float)d, 1.0f);
}
__global__ void fill_edges_kernel(const int* __restrict__ src, const int* __restrict__ dst) {
    int e = blockIdx.x * blockDim.x + threadIdx.x;
    if (e < N_EDGES) {
        int p = atomicAdd(&g_pos[dst[e]], 1);
        g_elist[p] = src[e];
    }
}

// ---------------- fp32 -> bf16 hi/lo split -----------------------------------
__device__ __forceinline__ void split1(float v, __nv_bfloat16& h, __nv_bfloat16& l) {
    h = __float2bfloat16_rn(v);
    l = __float2bfloat16_rn(v - __bfloat162float(h));
}

__global__ void split_kernel(const float* __restrict__ x,
                             __nv_bfloat16* __restrict__ hi,
                             __nv_bfloat16* __restrict__ lo, int n4) {
    int i = blockIdx.x * blockDim.x + threadIdx.x;
    if (i >= n4) return;
    float4 v = ((const float4*)x)[i];
    __align__(8) __nv_bfloat16 h[4], l[4];
    split1(v.x, h[0], l[0]); split1(v.y, h[1], l[1]);
    split1(v.z, h[2], l[2]); split1(v.w, h[3], l[3]);
    ((uint2*)hi)[i] = *(uint2*)h;
    ((uint2*)lo)[i] = *(uint2*)l;
}

// transpose + split all six 128x128 weights ([n][k] layout)
__global__ void prep_w_all_kernel(const float* __restrict__ W0, const float* __restrict__ W1,
                                  const float* __restrict__ W2, const float* __restrict__ W3,
                                  const float* __restrict__ W4, const float* __restrict__ W5,
                                  __nv_bfloat16* __restrict__ wts) {
    int t = blockIdx.x * blockDim.x + threadIdx.x;
    if (t >= 6 * F * F) return;
    int w = t / (F * F), r = t % (F * F);
    int n = r >> 7, k = r & 127;
    const float* Wp[6] = {W0, W1, W2, W3, W4, W5};
    float v = Wp[w][k * F + n];
    __nv_bfloat16 h, l;
    split1(v, h, l);
    int layer = w >> 1, sn = w & 1;
    size_t base = ((size_t)layer * 4 + sn * 2) * F * F;
    wts[base + r]         = h;
    wts[base + F * F + r] = l;
}

// ---------------- fused gather + dual-GEMM kernel ----------------------------
// Per block: 128 output rows.
// Phase 1: gather neighbor means (fp32) -> resident smem Mhi/Mlo (bf16, ldm layout)
// Phase 2: 24 K=32 chunks over 6 segments (order: Mhi*Wnhi, Mhi*Wnlo, Mlo*Wnhi,
//          Xhi*Wshi, Xhi*Wslo, Xlo*Wshi); M segs read A from resident smem,
//          X segs cp.async A from global; B always cp.async (8KB tiles).
// smem: resident 64KB + 2 stages x 16KB = 96KB -> 2 blocks/SM.
#define RES_BYTES 65536
#define STAGE_BYTES 16384
#define NCHUNK 24
__global__ void __launch_bounds__(256, 2)
sage_fused(const __nv_bfloat16* __restrict__ Xhi,
           const __nv_bfloat16* __restrict__ Xlo,
           const __nv_bfloat16* __restrict__ Wb,   // Wshi,Wslo,Wnhi,Wnlo ([n][k])
           const float* __restrict__ bias,
           __nv_bfloat16* __restrict__ Ohi,
           __nv_bfloat16* __restrict__ Olo,
           float* __restrict__ Ofp,
           int do_relu, int write_fp) {
    extern __shared__ __align__(16) char sm[];
    __shared__ float s_bias[F];

    int tid = threadIdx.x, lane = tid & 31, wid = tid >> 5;
    int warp_m = wid & 3, warp_n = wid >> 2;
    int row0 = blockIdx.x * 128;
    uint32_t smb = smem_u32(sm);

    if (tid < F) s_bias[tid] = bias[tid];

    // ---- phase 1: gather (warp per row, 16 rows per warp) ----
    {
        int co = lane * 4;
        for (int rr = 0; rr < 16; rr++) {
            int row = wid * 16 + rr;
            int gr  = row0 + row;
            float a0 = 0.f, a1 = 0.f, a2 = 0.f, a3 = 0.f;
            if (gr < N_NODES) {
                int s0 = g_start[gr], d = g_deg[gr];
                for (int j = 0; j < d; j++) {
                    int s = g_elist[s0 + j];
                    uint2 uh = *(const uint2*)(Xhi + (size_t)s * F + co);
                    uint2 ul = *(const uint2*)(Xlo + (size_t)s * F + co);
                    float2 h0 = __bfloat1622float2(*(__nv_bfloat162*)&uh.x);
                    float2 h1 = __bfloat1622float2(*(__nv_bfloat162*)&uh.y);
                    float2 l0 = __bfloat1622float2(*(__nv_bfloat162*)&ul.x);
                    float2 l1 = __bfloat1622float2(*(__nv_bfloat162*)&ul.y);
                    a0 += h0.x + l0.x; a1 += h0.y + l0.y;
                    a2 += h1.x + l1.x; a3 += h1.y + l1.y;
                }
                float iv = g_inv[gr];
                a0 *= iv; a1 *= iv; a2 *= iv; a3 *= iv;
            }
            __align__(8) __nv_bfloat16 h[4], l[4];
            split1(a0, h[0], l[0]); split1(a1, h[1], l[1]);
            split1(a2, h[2], l[2]); split1(a3, h[3], l[3]);
            // resident layout: pitch 256B, quad swizzle q ^ (row&7); lane covers 8B
            uint32_t off = (uint32_t)(row * 256 + (((lane >> 1) ^ (row & 7)) * 16) + (lane & 1) * 8);
            *(uint2*)(sm + off)             = *(uint2*)h;
            *(uint2*)(sm + RES_BYTES / 2 + off) = *(uint2*)l;  // Mlo at +32KB
        }
    }
    __syncthreads();

    // ---- phase 2: pipelined MMA over 24 chunks ----
    // segment order: 3,4,5 (resident M) then 0,1,2 (streamed X)
    // seg -> B slot in Wb: {0:Wshi,1:Wslo,2:Wshi,3:Wnhi,4:Wnlo,5:Wnhi}
    float acc[2][8][4];
#pragma unroll
    for (int i = 0; i < 2; i++)
#pragma unroll
        for (int j = 0; j < 8; j++)
#pragma unroll
            for (int k = 0; k < 4; k++) acc[i][j][k] = 0.f;

    auto seg_of   = [](int c) { const int S[6] = {3, 4, 5, 0, 1, 2}; return S[c >> 2]; };
    auto bslot_of = [](int seg) { const int B[6] = {0, 1, 0, 2, 3, 2}; return B[seg]; };

    auto load_chunk = [&](int c, int stg) {
        int seg = seg_of(c);
        int kq  = (c & 3) * 32;
        uint32_t stA = smb + RES_BYTES + stg * STAGE_BYTES;
        uint32_t stB = stA + 8192;
        const __nv_bfloat16* Bg = Wb + (size_t)bslot_of(seg) * F * F;
#pragma unroll
        for (int i = 0; i < 2; i++) {
            int idx = tid + i * 256;            // 512 quads (8KB)
            int rown = idx >> 2, q = idx & 3;
            uint32_t sw = (uint32_t)(rown * 64 + ((q ^ ((rown >> 1) & 3)) * 16));
            cp_async16(stB + sw, Bg + (size_t)rown * F + kq + q * 8, 16u);
        }
        if (seg < 3) {
            const __nv_bfloat16* Ag = (seg == 2) ? Xlo : Xhi;
#pragma unroll
            for (int i = 0; i < 2; i++) {
                int idx = tid + i * 256;
                int rown = idx >> 2, q = idx & 3;
                uint32_t sw = (uint32_t)(rown * 64 + ((q ^ ((rown >> 1) & 3)) * 16));
                int gr = row0 + rown;
                int grc = (gr < N_NODES) ? gr : 0;
                uint32_t p = (gr < N_NODES) ? 16u : 0u;
                cp_async16(stA + sw, Ag + (size_t)grc * F + kq + q * 8, p);
            }
        }
        cp_commit();
    };

    auto compute_chunk = [&](int c, int stg) {
        int seg = seg_of(c);
        int kq  = (c & 3) * 32;
        uint32_t stA = smb + RES_BYTES + stg * STAGE_BYTES;
        uint32_t stB = stA + 8192;
        bool res = (seg >= 3);
        uint32_t resb = smb + ((seg == 5) ? RES_BYTES / 2 : 0);
#pragma unroll
        for (int ks = 0; ks < 32; ks += 16) {
            uint32_t af[2][4];
#pragma unroll
            for (int ms = 0; ms < 2; ms++) {
                int r = warp_m * 32 + ms * 16 + (lane & 15);
                if (res) {
                    int qc = ((kq + ks) >> 3) + (lane >> 4);
                    ldm_x4(af[ms], resb + r * 256 + ((qc ^ (r & 7)) * 16));
                } else {
                    int q = (ks >> 3) + (lane >> 4);
                    ldm_x4(af[ms], stA + r * 64 + ((q ^ ((r >> 1) & 3)) * 16));
                }
            }
            uint32_t bf[4][4];
#pragma unroll
            for (int np = 0; np < 4; np++) {
                int n = warp_n * 64 + np * 16 + (lane & 7) + ((lane >> 4) << 3);
                int q = (ks >> 3) + ((lane >> 3) & 1);
                ldm_x4(bf[np], stB + n * 64 + ((q ^ ((n >> 1) & 3)) * 16));
            }
#pragma unroll
            for (int ms = 0; ms < 2; ms++)
#pragma unroll
                for (int np = 0; np < 4; np++) {
                    mma_bf16(acc[ms][np * 2 + 0], af[ms], bf[np][0], bf[np][1]);
                    mma_bf16(acc[ms][np * 2 + 1], af[ms], bf[np][2], bf[np][3]);
                }
        }
    };

    load_chunk(0, 0);
    for (int c = 0; c < NCHUNK; c++) {
        if (c + 1 < NCHUNK) {
            load_chunk(c + 1, (c + 1) & 1);
            cp_wait<1>();
        } else {
            cp_wait<0>();
        }
        __syncthreads();
        compute_chunk(c, c & 1);
        __syncthreads();
    }

    // ---- epilogue: bias + relu + (split-bf16 | fp32) writes ----
#pragma unroll
    for (int ms = 0; ms < 2; ms++) {
#pragma unroll
        for (int half = 0; half < 2; half++) {
            int gr = row0 + warp_m * 32 + ms * 16 + (lane >> 2) + half * 8;
            if (gr >= N_NODES) continue;
#pragma unroll
            for (int np = 0; np < 8; np++) {
                int col = warp_n * 64 + np * 8 + (lane & 3) * 2;
                float v0 = acc[ms][np][half * 2 + 0] + s_bias[col];
                float v1 = acc[ms][np][half * 2 + 1] + s_bias[col + 1];
                if (do_relu) { v0 = fmaxf(v0, 0.f); v1 = fmaxf(v1, 0.f); }
                size_t gi = (size_t)gr * F + col;
                if (write_fp) {
                    *(float2*)(Ofp + gi) = make_float2(v0, v1);
                } else {
                    __nv_bfloat16 h0, l0, h1, l1;
                    split1(v0, h0, l0); split1(v1, h1, l1);
                    __nv_bfloat162 hh; hh.x = h0; hh.y = h1;
                    __nv_bfloat162 ll; ll.x = l0; ll.y = l1;
                    *(__nv_bfloat162*)(Ohi + gi) = hh;
                    *(__nv_bfloat162*)(Olo + gi) = ll;
                }
            }
        }
    }
}

// ---------------- launch -----------------------------------------------------
extern "C" void kernel_launch(void* const* d_in, const int* in_sizes, int n_in,
                              void* d_out, int out_size) {
    const float* feat = (const float*)d_in[0];
    const int*   src  = (const int*)d_in[1];
    const int*   dst  = (const int*)d_in[2];
    const float* Wsl[3] = {(const float*)d_in[3], (const float*)d_in[6], (const float*)d_in[9]};
    const float* Wnl[3] = {(const float*)d_in[4], (const float*)d_in[7], (const float*)d_in[10]};
    const float* bl[3]  = {(const float*)d_in[5], (const float*)d_in[8], (const float*)d_in[11]};
    float* out = (float*)d_out;

    __nv_bfloat16 *a0hi, *a0lo, *a1hi, *a1lo, *a2hi, *a2lo, *wts;
    cudaGetSymbolAddress((void**)&a0hi, g_a0hi);
    cudaGetSymbolAddress((void**)&a0lo, g_a0lo);
    cudaGetSymbolAddress((void**)&a1hi, g_a1hi);
    cudaGetSymbolAddress((void**)&a1lo, g_a1lo);
    cudaGetSymbolAddress((void**)&a2hi, g_a2hi);
    cudaGetSymbolAddress((void**)&a2lo, g_a2lo);
    cudaGetSymbolAddress((void**)&wts,  g_wts);

    const int DSM = RES_BYTES + 2 * STAGE_BYTES;  // 96KB
    cudaFuncSetAttribute(sage_fused, cudaFuncAttributeMaxDynamicSharedMemorySize, DSM);

    const int TB = 256;

    // CSR build (scan-free)
    zero_deg_kernel<<<(N_NODES + TB - 1) / TB, TB>>>();
    count_deg_kernel<<<(N_EDGES + TB - 1) / TB, TB>>>(dst);
    assign_start_kernel<<<(N_NODES + TB - 1) / TB, TB>>>();
    fill_edges_kernel<<<(N_EDGES + TB - 1) / TB, TB>>>(src, dst);

    // feature + weight splits
    int n4 = N_NODES * F / 4;
    split_kernel<<<(n4 + TB - 1) / TB, TB>>>(feat, a0hi, a0lo, n4);
    prep_w_all_kernel<<<(6 * F * F + TB - 1) / TB, TB>>>(
        Wsl[0], Wnl[0], Wsl[1], Wnl[1], Wsl[2], Wnl[2], wts);

    const int grid = (N_NODES + 127) / 128;

    sage_fused<<<grid, 256, DSM>>>(a0hi, a0lo, wts + 0 * 4 * F * F, bl[0],
                                   a1hi, a1lo, out, 1, 0);
    sage_fused<<<grid, 256, DSM>>>(a1hi, a1lo, wts + 1 * 4 * F * F, bl[1],
                                   a2hi, a2lo, out, 1, 0);
    sage_fused<<<grid, 256, DSM>>>(a2hi, a2lo, wts + 2 * 4 * F * F, bl[2],
                                   a1hi, a1lo, out, 0, 1);
}

// round 6
// speedup vs baseline: 1.4446x; 1.4446x over previous
#include <cuda_runtime.h>
#include <cuda_bf16.h>
#include <cstdint>
#include <cstddef>

#define N_NODES 50000
#define N_EDGES 600000
#define F 128

// ---------------- scratch (static device globals) ----------------------------
__device__ int   g_deg[N_NODES];
__device__ int   g_start[N_NODES];
__device__ int   g_pos[N_NODES];
__device__ float g_inv[N_NODES];
__device__ int   g_elist[N_EDGES];
__device__ int   g_total;

__device__ __align__(16) __nv_bfloat16 g_a0hi[N_NODES * F];
__device__ __align__(16) __nv_bfloat16 g_a0lo[N_NODES * F];
__device__ __align__(16) __nv_bfloat16 g_a1hi[N_NODES * F];
__device__ __align__(16) __nv_bfloat16 g_a1lo[N_NODES * F];
__device__ __align__(16) __nv_bfloat16 g_a2hi[N_NODES * F];
__device__ __align__(16) __nv_bfloat16 g_a2lo[N_NODES * F];
__device__ __align__(16) __nv_bfloat16 g_mhi[N_NODES * F];
__device__ __align__(16) __nv_bfloat16 g_mlo[N_NODES * F];
__device__ __align__(16) float         g_P[N_NODES * F];
__device__ __align__(16) __nv_bfloat16 g_wts[12 * F * F];  // per layer: Wshi,Wslo,Wnhi,Wnlo

// ---------------- helpers ----------------------------------------------------
__device__ __forceinline__ uint32_t smem_u32(const void* p) {
    uint32_t a;
    asm("{ .reg .u64 t; cvta.to.shared.u64 t, %1; cvt.u32.u64 %0, t; }" : "=r"(a) : "l"(p));
    return a;
}
__device__ __forceinline__ void cp_async16(uint32_t dst, const void* src, uint32_t pbytes) {
    asm volatile("cp.async.cg.shared.global [%0], [%1], 16, %2;"
                 :: "r"(dst), "l"(src), "r"(pbytes));
}
__device__ __forceinline__ void cp_commit() { asm volatile("cp.async.commit_group;"); }
template <int N>
__device__ __forceinline__ void cp_wait() { asm volatile("cp.async.wait_group %0;" :: "n"(N)); }

__device__ __forceinline__ void ldm_x4(uint32_t* r, uint32_t addr) {
    asm volatile("ldmatrix.sync.aligned.m8n8.x4.shared.b16 {%0,%1,%2,%3}, [%4];"
                 : "=r"(r[0]), "=r"(r[1]), "=r"(r[2]), "=r"(r[3]) : "r"(addr));
}
__device__ __forceinline__ void mma_bf16(float* d, const uint32_t* a, uint32_t b0, uint32_t b1) {
    asm volatile("mma.sync.aligned.m16n8k16.row.col.f32.bf16.bf16.f32 "
                 "{%0,%1,%2,%3}, {%4,%5,%6,%7}, {%8,%9}, {%0,%1,%2,%3};"
                 : "+f"(d[0]), "+f"(d[1]), "+f"(d[2]), "+f"(d[3])
                 : "r"(a[0]), "r"(a[1]), "r"(a[2]), "r"(a[3]), "r"(b0), "r"(b1));
}

// ---------------- CSR build (scan-free) --------------------------------------
__global__ void zero_deg_kernel() {
    int i = blockIdx.x * blockDim.x + threadIdx.x;
    if (i < N_NODES) g_deg[i] = 0;
    if (i == 0) g_total = 0;
}
__global__ void count_deg_kernel(const int* __restrict__ dst) {
    int e = blockIdx.x * blockDim.x + threadIdx.x;
    if (e < N_EDGES) atomicAdd(&g_deg[dst[e]], 1);
}
__global__ void assign_start_kernel() {
    int i = blockIdx.x * blockDim.x + threadIdx.x;
    if (i >= N_NODES) return;
    int d = g_deg[i];
    int s = atomicAdd(&g_total, d);
    g_start[i] = s;
    g_pos[i]   = s;
    g_inv[i]   = 1.0f / fmaxf((float)d, 1.0f);
}
__global__ void fill_edges_kernel(const int* __restrict__ src, const int* __restrict__ dst) {
    int e = blockIdx.x * blockDim.x + threadIdx.x;
    if (e < N_EDGES) {
        int p = atomicAdd(&g_pos[dst[e]], 1);
        g_elist[p] = src[e];
    }
}

// ---------------- fp32 -> bf16 hi/lo split -----------------------------------
__device__ __forceinline__ void split1(float v, __nv_bfloat16& h, __nv_bfloat16& l) {
    h = __float2bfloat16_rn(v);
    l = __float2bfloat16_rn(v - __bfloat162float(h));
}

__global__ void split_kernel(const float* __restrict__ x,
                             __nv_bfloat16* __restrict__ hi,
                             __nv_bfloat16* __restrict__ lo, int n4) {
    int i = blockIdx.x * blockDim.x + threadIdx.x;
    if (i >= n4) return;
    float4 v = ((const float4*)x)[i];
    __align__(8) __nv_bfloat16 h[4], l[4];
    split1(v.x, h[0], l[0]); split1(v.y, h[1], l[1]);
    split1(v.z, h[2], l[2]); split1(v.w, h[3], l[3]);
    ((uint2*)hi)[i] = *(uint2*)h;
    ((uint2*)lo)[i] = *(uint2*)l;
}

// transpose + split all six 128x128 weights ([n][k] layout)
__global__ void prep_w_all_kernel(const float* __restrict__ W0, const float* __restrict__ W1,
                                  const float* __restrict__ W2, const float* __restrict__ W3,
                                  const float* __restrict__ W4, const float* __restrict__ W5,
                                  __nv_bfloat16* __restrict__ wts) {
    int t = blockIdx.x * blockDim.x + threadIdx.x;
    if (t >= 6 * F * F) return;
    int w = t / (F * F), r = t % (F * F);
    int n = r >> 7, k = r & 127;
    const float* Wp[6] = {W0, W1, W2, W3, W4, W5};
    float v = Wp[w][k * F + n];
    __nv_bfloat16 h, l;
    split1(v, h, l);
    int layer = w >> 1, sn = w & 1;
    size_t base = ((size_t)layer * 4 + sn * 2) * F * F;
    wts[base + r]         = h;
    wts[base + F * F + r] = l;
}

// ---------------- mean aggregation (warp per node) ---------------------------
__global__ void agg_bf16_kernel(const __nv_bfloat16* __restrict__ xhi,
                                const __nv_bfloat16* __restrict__ xlo) {
    int w    = (blockIdx.x * blockDim.x + threadIdx.x) >> 5;
    int lane = threadIdx.x & 31;
    if (w >= N_NODES) return;
    int s0 = g_start[w];
    int d  = g_deg[w];
    int co = lane * 4;
    float a0 = 0.f, a1 = 0.f, a2 = 0.f, a3 = 0.f;
    for (int j = 0; j < d; j++) {
        int s = g_elist[s0 + j];
        uint2 uh = *(const uint2*)(xhi + (size_t)s * F + co);
        uint2 ul = *(const uint2*)(xlo + (size_t)s * F + co);
        float2 h0 = __bfloat1622float2(*(__nv_bfloat162*)&uh.x);
        float2 h1 = __bfloat1622float2(*(__nv_bfloat162*)&uh.y);
        float2 l0 = __bfloat1622float2(*(__nv_bfloat162*)&ul.x);
        float2 l1 = __bfloat1622float2(*(__nv_bfloat162*)&ul.y);
        a0 += h0.x + l0.x; a1 += h0.y + l0.y;
        a2 += h1.x + l1.x; a3 += h1.y + l1.y;
    }
    float iv = g_inv[w];
    __align__(8) __nv_bfloat16 h[4], l[4];
    split1(a0 * iv, h[0], l[0]); split1(a1 * iv, h[1], l[1]);
    split1(a2 * iv, h[2], l[2]); split1(a3 * iv, h[3], l[3]);
    *(uint2*)(g_mhi + (size_t)w * F + co) = *(uint2*)h;
    *(uint2*)(g_mlo + (size_t)w * F + co) = *(uint2*)l;
}

// layer-1 variant: reads fp32 features directly (no dependency on split)
__global__ void agg_f32_kernel(const float* __restrict__ x) {
    int w    = (blockIdx.x * blockDim.x + threadIdx.x) >> 5;
    int lane = threadIdx.x & 31;
    if (w >= N_NODES) return;
    int s0 = g_start[w];
    int d  = g_deg[w];
    int co = lane * 4;
    float a0 = 0.f, a1 = 0.f, a2 = 0.f, a3 = 0.f;
    for (int j = 0; j < d; j++) {
        int s = g_elist[s0 + j];
        float4 v = *(const float4*)(x + (size_t)s * F + co);
        a0 += v.x; a1 += v.y; a2 += v.z; a3 += v.w;
    }
    float iv = g_inv[w];
    __align__(8) __nv_bfloat16 h[4], l[4];
    split1(a0 * iv, h[0], l[0]); split1(a1 * iv, h[1], l[1]);
    split1(a2 * iv, h[2], l[2]); split1(a3 * iv, h[3], l[3]);
    *(uint2*)(g_mhi + (size_t)w * F + co) = *(uint2*)h;
    *(uint2*)(g_mlo + (size_t)w * F + co) = *(uint2*)l;
}

// ---------------- half-GEMM: out = [relu](A@W(hi/lo 3-seg) [+bias] [+Pin]) ----
// block 128x128, 8 warps 4(m)x2(n); 3 segments {hi*Whi, hi*Wlo, lo*Whi},
// 6 K=64 chunks, 3-stage cp.async pipeline (proven R4 structure).
#define STAGE_BYTES 32768
#define NSTAGE 3
#define NCHUNK 6
__global__ void __launch_bounds__(256, 2)
sage_half_gemm(const __nv_bfloat16* __restrict__ Ahi,
               const __nv_bfloat16* __restrict__ Alo,
               const __nv_bfloat16* __restrict__ Wpair,  // hi at 0, lo at F*F ([n][k])
               const float* __restrict__ bias,           // nullable
               const float* __restrict__ Pin,            // nullable fp32 addend
               __nv_bfloat16* __restrict__ Ohi,
               __nv_bfloat16* __restrict__ Olo,
               float* __restrict__ Ofp,
               int do_relu, int write_fp) {
    extern __shared__ __align__(16) char sm[];
    __shared__ float s_bias[F];

    int tid = threadIdx.x, lane = tid & 31, wid = tid >> 5;
    int warp_m = wid & 3, warp_n = wid >> 2;
    int row0 = blockIdx.x * 128;

    if (tid < F) s_bias[tid] = bias ? bias[tid] : 0.f;

    const int BI[3] = {0, 1, 0};
    uint32_t smb = smem_u32(sm);

    float acc[2][8][4];
#pragma unroll
    for (int i = 0; i < 2; i++)
#pragma unroll
        for (int j = 0; j < 8; j++)
#pragma unroll
            for (int k = 0; k < 4; k++) acc[i][j][k] = 0.f;

    auto load_chunk = [&](int c, int stg) {
        int seg = c >> 1;
        int kc  = (c & 1) * 64;
        const __nv_bfloat16* Ag = (seg == 2) ? Alo : Ahi;
        const __nv_bfloat16* Bg = Wpair + (size_t)BI[seg] * F * F;
        uint32_t aB = smb + stg * STAGE_BYTES;
        uint32_t bB = aB + 16384;
#pragma unroll
        for (int i = 0; i < 4; i++) {
            int idx = tid + i * 256;
            int row = idx >> 3, q = idx & 7;
            uint32_t sw = (uint32_t)(row * 128 + ((q ^ (row & 7)) * 16));
            int gr = row0 + row;
            int grc = (gr < N_NODES) ? gr : 0;
            uint32_t p = (gr < N_NODES) ? 16u : 0u;
            cp_async16(aB + sw, Ag + (size_t)grc * F + kc + q * 8, p);
            cp_async16(bB + sw, Bg + (size_t)row * F + kc + q * 8, 16u);
        }
        cp_commit();
    };

    auto compute = [&](int stg) {
        uint32_t aB = smb + stg * STAGE_BYTES;
        uint32_t bB = aB + 16384;
#pragma unroll
        for (int ks = 0; ks < 64; ks += 16) {
            uint32_t af[2][4];
#pragma unroll
            for (int ms = 0; ms < 2; ms++) {
                int r = warp_m * 32 + ms * 16 + (lane & 15);
                int q = (ks >> 3) + (lane >> 4);
                ldm_x4(af[ms], aB + r * 128 + ((q ^ (r & 7)) * 16));
            }
            uint32_t bf[4][4];
#pragma unroll
            for (int np = 0; np < 4; np++) {
                int n = warp_n * 64 + np * 16 + (lane & 7) + ((lane >> 4) << 3);
                int q = (ks >> 3) + ((lane >> 3) & 1);
                ldm_x4(bf[np], bB + n * 128 + ((q ^ (n & 7)) * 16));
            }
#pragma unroll
            for (int ms = 0; ms < 2; ms++)
#pragma unroll
                for (int np = 0; np < 4; np++) {
                    mma_bf16(acc[ms][np * 2 + 0], af[ms], bf[np][0], bf[np][1]);
                    mma_bf16(acc[ms][np * 2 + 1], af[ms], bf[np][2], bf[np][3]);
                }
        }
    };

    load_chunk(0, 0);
    load_chunk(1, 1);
    for (int c = 0; c < NCHUNK; c++) {
        if (c + 1 < NCHUNK) cp_wait<1>(); else cp_wait<0>();
        __syncthreads();
        if (c + 2 < NCHUNK) load_chunk(c + 2, (c + 2) % NSTAGE);
        compute(c % NSTAGE);
    }

    // epilogue
#pragma unroll
    for (int ms = 0; ms < 2; ms++) {
#pragma unroll
        for (int half = 0; half < 2; half++) {
            int gr = row0 + warp_m * 32 + ms * 16 + (lane >> 2) + half * 8;
            if (gr >= N_NODES) continue;
#pragma unroll
            for (int np = 0; np < 8; np++) {
                int col = warp_n * 64 + np * 8 + (lane & 3) * 2;
                size_t gi = (size_t)gr * F + col;
                float v0 = acc[ms][np][half * 2 + 0] + s_bias[col];
                float v1 = acc[ms][np][half * 2 + 1] + s_bias[col + 1];
                if (Pin) {
                    float2 pv = *(const float2*)(Pin + gi);
                    v0 += pv.x; v1 += pv.y;
                }
                if (do_relu) { v0 = fmaxf(v0, 0.f); v1 = fmaxf(v1, 0.f); }
                if (write_fp) {
                    *(float2*)(Ofp + gi) = make_float2(v0, v1);
                } else {
                    __nv_bfloat16 h0, l0, h1, l1;
                    split1(v0, h0, l0); split1(v1, h1, l1);
                    __nv_bfloat162 hh; hh.x = h0; hh.y = h1;
                    __nv_bfloat162 ll; ll.x = l0; ll.y = l1;
                    *(__nv_bfloat162*)(Ohi + gi) = hh;
                    *(__nv_bfloat162*)(Olo + gi) = ll;
                }
            }
        }
    }
}

// ---------------- streams / events (created once, before harness checkpoints) -
static cudaStream_t g_s2 = nullptr;
static cudaEvent_t  g_ev[8];
struct _StreamInit {
    _StreamInit() {
        cudaStreamCreateWithFlags(&g_s2, cudaStreamNonBlocking);
        for (int i = 0; i < 8; i++)
            cudaEventCreateWithFlags(&g_ev[i], cudaEventDisableTiming);
    }
};
static _StreamInit _stream_init;

// ---------------- launch -----------------------------------------------------
extern "C" void kernel_launch(void* const* d_in, const int* in_sizes, int n_in,
                              void* d_out, int out_size) {
    const float* feat = (const float*)d_in[0];
    const int*   src  = (const int*)d_in[1];
    const int*   dst  = (const int*)d_in[2];
    const float* Wsl[3] = {(const float*)d_in[3], (const float*)d_in[6], (const float*)d_in[9]};
    const float* Wnl[3] = {(const float*)d_in[4], (const float*)d_in[7], (const float*)d_in[10]};
    const float* bl[3]  = {(const float*)d_in[5], (const float*)d_in[8], (const float*)d_in[11]};
    float* out = (float*)d_out;

    __nv_bfloat16 *a0hi, *a0lo, *a1hi, *a1lo, *a2hi, *a2lo, *mhi, *mlo, *wts;
    float* Pbuf;
    cudaGetSymbolAddress((void**)&a0hi, g_a0hi);
    cudaGetSymbolAddress((void**)&a0lo, g_a0lo);
    cudaGetSymbolAddress((void**)&a1hi, g_a1hi);
    cudaGetSymbolAddress((void**)&a1lo, g_a1lo);
    cudaGetSymbolAddress((void**)&a2hi, g_a2hi);
    cudaGetSymbolAddress((void**)&a2lo, g_a2lo);
    cudaGetSymbolAddress((void**)&mhi,  g_mhi);
    cudaGetSymbolAddress((void**)&mlo,  g_mlo);
    cudaGetSymbolAddress((void**)&wts,  g_wts);
    cudaGetSymbolAddress((void**)&Pbuf, g_P);

    const int DSM = NSTAGE * STAGE_BYTES;  // 96KB
    cudaFuncSetAttribute(sage_half_gemm, cudaFuncAttributeMaxDynamicSharedMemorySize, DSM);

    const int TB = 256;
    const int aggGrid = (N_NODES * 32 + TB - 1) / TB;
    const int gmGrid  = (N_NODES + 127) / 128;
    cudaStream_t s0 = 0, s2 = g_s2;

    // fork s2 off the capture stream
    cudaEventRecord(g_ev[0], s0);
    cudaStreamWaitEvent(s2, g_ev[0], 0);

    // ---- s2: split + weight prep + self-GEMM layer 1 ----
    int n4 = N_NODES * F / 4;
    split_kernel<<<(n4 + TB - 1) / TB, TB, 0, s2>>>(feat, a0hi, a0lo, n4);
    prep_w_all_kernel<<<(6 * F * F + TB - 1) / TB, TB, 0, s2>>>(
        Wsl[0], Wnl[0], Wsl[1], Wnl[1], Wsl[2], Wnl[2], wts);
    sage_half_gemm<<<gmGrid, 256, DSM, s2>>>(a0hi, a0lo, wts + 0 * 4 * F * F,
                                             bl[0], nullptr, nullptr, nullptr, Pbuf, 0, 1);
    cudaEventRecord(g_ev[1], s2);

    // ---- s0: CSR build + layer-1 aggregation (fp32 features) ----
    zero_deg_kernel<<<(N_NODES + TB - 1) / TB, TB, 0, s0>>>();
    count_deg_kernel<<<(N_EDGES + TB - 1) / TB, TB, 0, s0>>>(dst);
    assign_start_kernel<<<(N_NODES + TB - 1) / TB, TB, 0, s0>>>();
    fill_edges_kernel<<<(N_EDGES + TB - 1) / TB, TB, 0, s0>>>(src, dst);
    agg_f32_kernel<<<aggGrid, TB, 0, s0>>>(feat);

    // join: neigh-GEMM layer 1 -> a1 (relu, split)
    cudaStreamWaitEvent(s0, g_ev[1], 0);
    sage_half_gemm<<<gmGrid, 256, DSM, s0>>>(mhi, mlo, wts + 0 * 4 * F * F + 2 * F * F,
                                             nullptr, Pbuf, a1hi, a1lo, nullptr, 1, 0);

    // ---- layer 2: agg(a1) || self-GEMM(a1) ----
    cudaEventRecord(g_ev[2], s0);
    cudaStreamWaitEvent(s2, g_ev[2], 0);
    sage_half_gemm<<<gmGrid, 256, DSM, s2>>>(a1hi, a1lo, wts + 1 * 4 * F * F,
                                             bl[1], nullptr, nullptr, nullptr, Pbuf, 0, 1);
    cudaEventRecord(g_ev[3], s2);
    agg_bf16_kernel<<<aggGrid, TB, 0, s0>>>(a1hi, a1lo);
    cudaStreamWaitEvent(s0, g_ev[3], 0);
    sage_half_gemm<<<gmGrid, 256, DSM, s0>>>(mhi, mlo, wts + 1 * 4 * F * F + 2 * F * F,
                                             nullptr, Pbuf, a2hi, a2lo, nullptr, 1, 0);

    // ---- layer 3: agg(a2) || self-GEMM(a2); final out fp32, no relu ----
    cudaEventRecord(g_ev[4], s0);
    cudaStreamWaitEvent(s2, g_ev[4], 0);
    sage_half_gemm<<<gmGrid, 256, DSM, s2>>>(a2hi, a2lo, wts + 2 * 4 * F * F,
                                             bl[2], nullptr, nullptr, nullptr, Pbuf, 0, 1);
    cudaEventRecord(g_ev[5], s2);
    agg_bf16_kernel<<<aggGrid, TB, 0, s0>>>(a2hi, a2lo);
    cudaStreamWaitEvent(s0, g_ev[5], 0);
    sage_half_gemm<<<gmGrid, 256, DSM, s0>>>(mhi, mlo, wts + 2 * 4 * F * F + 2 * F * F,
                                             nullptr, Pbuf, nullptr, nullptr, out, 0, 1);
}

// round 7
// speedup vs baseline: 1.5785x; 1.0927x over previous
#include <cuda_runtime.h>
#include <cuda_bf16.h>
#include <cstdint>
#include <cstddef>

#define N_NODES 50000
#define N_EDGES 600000
#define F 128

// ---------------- scratch (static device globals) ----------------------------
__device__ int   g_deg[N_NODES];
__device__ int   g_start[N_NODES];
__device__ int   g_pos[N_NODES];
__device__ float g_inv[N_NODES];
__device__ int   g_elist[N_EDGES];
__device__ int   g_total;

__device__ __align__(16) __nv_bfloat16 g_a0hi[N_NODES * F];
__device__ __align__(16) __nv_bfloat16 g_a0lo[N_NODES * F];
__device__ __align__(16) __nv_bfloat16 g_a1hi[N_NODES * F];
__device__ __align__(16) __nv_bfloat16 g_a1lo[N_NODES * F];
__device__ __align__(16) __nv_bfloat16 g_a2hi[N_NODES * F];
__device__ __align__(16) __nv_bfloat16 g_a2lo[N_NODES * F];
__device__ __align__(16) __nv_bfloat16 g_mhi[N_NODES * F];
__device__ __align__(16) __nv_bfloat16 g_mlo[N_NODES * F];
__device__ __align__(16) float         g_P[N_NODES * F];
__device__ __align__(16) __nv_bfloat16 g_wts[12 * F * F];  // per layer: Wshi,Wslo,Wnhi,Wnlo

// ---------------- helpers ----------------------------------------------------
__device__ __forceinline__ uint32_t smem_u32(const void* p) {
    uint32_t a;
    asm("{ .reg .u64 t; cvta.to.shared.u64 t, %1; cvt.u32.u64 %0, t; }" : "=r"(a) : "l"(p));
    return a;
}
__device__ __forceinline__ void cp_async16(uint32_t dst, const void* src, uint32_t pbytes) {
    asm volatile("cp.async.cg.shared.global [%0], [%1], 16, %2;"
                 :: "r"(dst), "l"(src), "r"(pbytes));
}
__device__ __forceinline__ void cp_commit() { asm volatile("cp.async.commit_group;"); }
template <int N>
__device__ __forceinline__ void cp_wait() { asm volatile("cp.async.wait_group %0;" :: "n"(N)); }

__device__ __forceinline__ void ldm_x4(uint32_t* r, uint32_t addr) {
    asm volatile("ldmatrix.sync.aligned.m8n8.x4.shared.b16 {%0,%1,%2,%3}, [%4];"
                 : "=r"(r[0]), "=r"(r[1]), "=r"(r[2]), "=r"(r[3]) : "r"(addr));
}
__device__ __forceinline__ void mma_bf16(float* d, const uint32_t* a, uint32_t b0, uint32_t b1) {
    asm volatile("mma.sync.aligned.m16n8k16.row.col.f32.bf16.bf16.f32 "
                 "{%0,%1,%2,%3}, {%4,%5,%6,%7}, {%8,%9}, {%0,%1,%2,%3};"
                 : "+f"(d[0]), "+f"(d[1]), "+f"(d[2]), "+f"(d[3])
                 : "r"(a[0]), "r"(a[1]), "r"(a[2]), "r"(a[3]), "r"(b0), "r"(b1));
}

// ---------------- CSR build (scan-free) --------------------------------------
__global__ void zero_deg_kernel() {
    int i = blockIdx.x * blockDim.x + threadIdx.x;
    if (i < N_NODES) g_deg[i] = 0;
    if (i == 0) g_total = 0;
}
__global__ void count_deg_kernel(const int* __restrict__ dst) {
    int e = blockIdx.x * blockDim.x + threadIdx.x;
    if (e < N_EDGES) atomicAdd(&g_deg[dst[e]], 1);
}
__global__ void assign_start_kernel() {
    int i = blockIdx.x * blockDim.x + threadIdx.x;
    if (i >= N_NODES) return;
    int d = g_deg[i];
    int s = atomicAdd(&g_total, d);
    g_start[i] = s;
    g_pos[i]   = s;
    g_inv[i]   = 1.0f / fmaxf((float)d, 1.0f);
}
__global__ void fill_edges_kernel(const int* __restrict__ src, const int* __restrict__ dst) {
    int e = blockIdx.x * blockDim.x + threadIdx.x;
    if (e < N_EDGES) {
        int p = atomicAdd(&g_pos[dst[e]], 1);
        g_elist[p] = src[e];
    }
}

// ---------------- fp32 -> bf16 hi/lo split -----------------------------------
__device__ __forceinline__ void split1(float v, __nv_bfloat16& h, __nv_bfloat16& l) {
    h = __float2bfloat16_rn(v);
    l = __float2bfloat16_rn(v - __bfloat162float(h));
}

__global__ void split_kernel(const float* __restrict__ x,
                             __nv_bfloat16* __restrict__ hi,
                             __nv_bfloat16* __restrict__ lo, int n4) {
    int i = blockIdx.x * blockDim.x + threadIdx.x;
    if (i >= n4) return;
    float4 v = ((const float4*)x)[i];
    __align__(8) __nv_bfloat16 h[4], l[4];
    split1(v.x, h[0], l[0]); split1(v.y, h[1], l[1]);
    split1(v.z, h[2], l[2]); split1(v.w, h[3], l[3]);
    ((uint2*)hi)[i] = *(uint2*)h;
    ((uint2*)lo)[i] = *(uint2*)l;
}

// transpose + split all six 128x128 weights ([n][k] layout)
__global__ void prep_w_all_kernel(const float* __restrict__ W0, const float* __restrict__ W1,
                                  const float* __restrict__ W2, const float* __restrict__ W3,
                                  const float* __restrict__ W4, const float* __restrict__ W5,
                                  __nv_bfloat16* __restrict__ wts) {
    int t = blockIdx.x * blockDim.x + threadIdx.x;
    if (t >= 6 * F * F) return;
    int w = t / (F * F), r = t % (F * F);
    int n = r >> 7, k = r & 127;
    const float* Wp[6] = {W0, W1, W2, W3, W4, W5};
    float v = Wp[w][k * F + n];
    __nv_bfloat16 h, l;
    split1(v, h, l);
    int layer = w >> 1, sn = w & 1;
    size_t base = ((size_t)layer * 4 + sn * 2) * F * F;
    wts[base + r]         = h;
    wts[base + F * F + r] = l;
}

// ---------------- mean aggregation (warp per node) ---------------------------
__global__ void agg_bf16_kernel(const __nv_bfloat16* __restrict__ xhi,
                                const __nv_bfloat16* __restrict__ xlo) {
    int w    = (blockIdx.x * blockDim.x + threadIdx.x) >> 5;
    int lane = threadIdx.x & 31;
    if (w >= N_NODES) return;
    int s0 = g_start[w];
    int d  = g_deg[w];
    int co = lane * 4;
    float a0 = 0.f, a1 = 0.f, a2 = 0.f, a3 = 0.f;
    for (int j = 0; j < d; j++) {
        int s = g_elist[s0 + j];
        uint2 uh = *(const uint2*)(xhi + (size_t)s * F + co);
        uint2 ul = *(const uint2*)(xlo + (size_t)s * F + co);
        float2 h0 = __bfloat1622float2(*(__nv_bfloat162*)&uh.x);
        float2 h1 = __bfloat1622float2(*(__nv_bfloat162*)&uh.y);
        float2 l0 = __bfloat1622float2(*(__nv_bfloat162*)&ul.x);
        float2 l1 = __bfloat1622float2(*(__nv_bfloat162*)&ul.y);
        a0 += h0.x + l0.x; a1 += h0.y + l0.y;
        a2 += h1.x + l1.x; a3 += h1.y + l1.y;
    }
    float iv = g_inv[w];
    __align__(8) __nv_bfloat16 h[4], l[4];
    split1(a0 * iv, h[0], l[0]); split1(a1 * iv, h[1], l[1]);
    split1(a2 * iv, h[2], l[2]); split1(a3 * iv, h[3], l[3]);
    *(uint2*)(g_mhi + (size_t)w * F + co) = *(uint2*)h;
    *(uint2*)(g_mlo + (size_t)w * F + co) = *(uint2*)l;
}

// layer-1 variant: reads fp32 features directly (no dependency on split)
__global__ void agg_f32_kernel(const float* __restrict__ x) {
    int w    = (blockIdx.x * blockDim.x + threadIdx.x) >> 5;
    int lane = threadIdx.x & 31;
    if (w >= N_NODES) return;
    int s0 = g_start[w];
    int d  = g_deg[w];
    int co = lane * 4;
    float a0 = 0.f, a1 = 0.f, a2 = 0.f, a3 = 0.f;
    for (int j = 0; j < d; j++) {
        int s = g_elist[s0 + j];
        float4 v = *(const float4*)(x + (size_t)s * F + co);
        a0 += v.x; a1 += v.y; a2 += v.z; a3 += v.w;
    }
    float iv = g_inv[w];
    __align__(8) __nv_bfloat16 h[4], l[4];
    split1(a0 * iv, h[0], l[0]); split1(a1 * iv, h[1], l[1]);
    split1(a2 * iv, h[2], l[2]); split1(a3 * iv, h[3], l[3]);
    *(uint2*)(g_mhi + (size_t)w * F + co) = *(uint2*)h;
    *(uint2*)(g_mlo + (size_t)w * F + co) = *(uint2*)l;
}

#define STAGE_BYTES 32768
#define NSTAGE 3

// ---------------- dual-GEMM (R4-proven): out = [relu](x@Ws + m@Wn + b) -------
#define DK_NCHUNK 12
__global__ void __launch_bounds__(256, 2)
sage_dual_gemm(const __nv_bfloat16* __restrict__ Ahi,
               const __nv_bfloat16* __restrict__ Alo,
               const __nv_bfloat16* __restrict__ Mhi,
               const __nv_bfloat16* __restrict__ Mlo,
               const __nv_bfloat16* __restrict__ Wb,   // Wshi,Wslo,Wnhi,Wnlo ([n][k])
               const float* __restrict__ bias,
               __nv_bfloat16* __restrict__ Ohi,
               __nv_bfloat16* __restrict__ Olo,
               float* __restrict__ Ofp,
               int do_relu, int write_fp) {
    extern __shared__ __align__(16) char sm[];
    __shared__ float s_bias[F];

    int tid = threadIdx.x, lane = tid & 31, wid = tid >> 5;
    int warp_m = wid & 3, warp_n = wid >> 2;
    int row0 = blockIdx.x * 128;

    if (tid < F) s_bias[tid] = bias[tid];

    const __nv_bfloat16* Aptr[4] = {Ahi, Alo, Mhi, Mlo};
    const int AI[6] = {0, 0, 1, 2, 2, 3};
    const int BI[6] = {0, 1, 0, 2, 3, 2};
    uint32_t smb = smem_u32(sm);

    float acc[2][8][4];
#pragma unroll
    for (int i = 0; i < 2; i++)
#pragma unroll
        for (int j = 0; j < 8; j++)
#pragma unroll
            for (int k = 0; k < 4; k++) acc[i][j][k] = 0.f;

    auto load_chunk = [&](int c, int stg) {
        int seg = c >> 1;
        int kc  = (c & 1) * 64;
        const __nv_bfloat16* Ag = Aptr[AI[seg]];
        const __nv_bfloat16* Bg = Wb + (size_t)BI[seg] * F * F;
        uint32_t aB = smb + stg * STAGE_BYTES;
        uint32_t bB = aB + 16384;
#pragma unroll
        for (int i = 0; i < 4; i++) {
            int idx = tid + i * 256;
            int row = idx >> 3, q = idx & 7;
            uint32_t sw = (uint32_t)(row * 128 + ((q ^ (row & 7)) * 16));
            int gr = row0 + row;
            int grc = (gr < N_NODES) ? gr : 0;
            uint32_t p = (gr < N_NODES) ? 16u : 0u;
            cp_async16(aB + sw, Ag + (size_t)grc * F + kc + q * 8, p);
            cp_async16(bB + sw, Bg + (size_t)row * F + kc + q * 8, 16u);
        }
        cp_commit();
    };

    auto compute = [&](int stg) {
        uint32_t aB = smb + stg * STAGE_BYTES;
        uint32_t bB = aB + 16384;
#pragma unroll
        for (int ks = 0; ks < 64; ks += 16) {
            uint32_t af[2][4];
#pragma unroll
            for (int ms = 0; ms < 2; ms++) {
                int r = warp_m * 32 + ms * 16 + (lane & 15);
                int q = (ks >> 3) + (lane >> 4);
                ldm_x4(af[ms], aB + r * 128 + ((q ^ (r & 7)) * 16));
            }
            uint32_t bf[4][4];
#pragma unroll
            for (int np = 0; np < 4; np++) {
                int n = warp_n * 64 + np * 16 + (lane & 7) + ((lane >> 4) << 3);
                int q = (ks >> 3) + ((lane >> 3) & 1);
                ldm_x4(bf[np], bB + n * 128 + ((q ^ (n & 7)) * 16));
            }
#pragma unroll
            for (int ms = 0; ms < 2; ms++)
#pragma unroll
                for (int np = 0; np < 4; np++) {
                    mma_bf16(acc[ms][np * 2 + 0], af[ms], bf[np][0], bf[np][1]);
                    mma_bf16(acc[ms][np * 2 + 1], af[ms], bf[np][2], bf[np][3]);
                }
        }
    };

    load_chunk(0, 0);
    load_chunk(1, 1);
    for (int c = 0; c < DK_NCHUNK; c++) {
        if (c + 1 < DK_NCHUNK) cp_wait<1>(); else cp_wait<0>();
        __syncthreads();
        if (c + 2 < DK_NCHUNK) load_chunk(c + 2, (c + 2) % NSTAGE);
        compute(c % NSTAGE);
    }

#pragma unroll
    for (int ms = 0; ms < 2; ms++) {
#pragma unroll
        for (int half = 0; half < 2; half++) {
            int gr = row0 + warp_m * 32 + ms * 16 + (lane >> 2) + half * 8;
            if (gr >= N_NODES) continue;
#pragma unroll
            for (int np = 0; np < 8; np++) {
                int col = warp_n * 64 + np * 8 + (lane & 3) * 2;
                float v0 = acc[ms][np][half * 2 + 0] + s_bias[col];
                float v1 = acc[ms][np][half * 2 + 1] + s_bias[col + 1];
                if (do_relu) { v0 = fmaxf(v0, 0.f); v1 = fmaxf(v1, 0.f); }
                size_t gi = (size_t)gr * F + col;
                if (write_fp) {
                    *(float2*)(Ofp + gi) = make_float2(v0, v1);
                } else {
                    __nv_bfloat16 h0, l0, h1, l1;
                    split1(v0, h0, l0); split1(v1, h1, l1);
                    __nv_bfloat162 hh; hh.x = h0; hh.y = h1;
                    __nv_bfloat162 ll; ll.x = l0; ll.y = l1;
                    *(__nv_bfloat162*)(Ohi + gi) = hh;
                    *(__nv_bfloat162*)(Olo + gi) = ll;
                }
            }
        }
    }
}

// ---------------- half-GEMM (R6-proven; used for layer 1 only) ---------------
#define HK_NCHUNK 6
__global__ void __launch_bounds__(256, 2)
sage_half_gemm(const __nv_bfloat16* __restrict__ Ahi,
               const __nv_bfloat16* __restrict__ Alo,
               const __nv_bfloat16* __restrict__ Wpair,  // hi at 0, lo at F*F ([n][k])
               const float* __restrict__ bias,           // nullable
               const float* __restrict__ Pin,            // nullable fp32 addend
               __nv_bfloat16* __restrict__ Ohi,
               __nv_bfloat16* __restrict__ Olo,
               float* __restrict__ Ofp,
               int do_relu, int write_fp) {
    extern __shared__ __align__(16) char sm[];
    __shared__ float s_bias[F];

    int tid = threadIdx.x, lane = tid & 31, wid = tid >> 5;
    int warp_m = wid & 3, warp_n = wid >> 2;
    int row0 = blockIdx.x * 128;

    if (tid < F) s_bias[tid] = bias ? bias[tid] : 0.f;

    const int BI[3] = {0, 1, 0};
    uint32_t smb = smem_u32(sm);

    float acc[2][8][4];
#pragma unroll
    for (int i = 0; i < 2; i++)
#pragma unroll
        for (int j = 0; j < 8; j++)
#pragma unroll
            for (int k = 0; k < 4; k++) acc[i][j][k] = 0.f;

    auto load_chunk = [&](int c, int stg) {
        int seg = c >> 1;
        int kc  = (c & 1) * 64;
        const __nv_bfloat16* Ag = (seg == 2) ? Alo : Ahi;
        const __nv_bfloat16* Bg = Wpair + (size_t)BI[seg] * F * F;
        uint32_t aB = smb + stg * STAGE_BYTES;
        uint32_t bB = aB + 16384;
#pragma unroll
        for (int i = 0; i < 4; i++) {
            int idx = tid + i * 256;
            int row = idx >> 3, q = idx & 7;
            uint32_t sw = (uint32_t)(row * 128 + ((q ^ (row & 7)) * 16));
            int gr = row0 + row;
            int grc = (gr < N_NODES) ? gr : 0;
            uint32_t p = (gr < N_NODES) ? 16u : 0u;
            cp_async16(aB + sw, Ag + (size_t)grc * F + kc + q * 8, p);
            cp_async16(bB + sw, Bg + (size_t)row * F + kc + q * 8, 16u);
        }
        cp_commit();
    };

    auto compute = [&](int stg) {
        uint32_t aB = smb + stg * STAGE_BYTES;
        uint32_t bB = aB + 16384;
#pragma unroll
        for (int ks = 0; ks < 64; ks += 16) {
            uint32_t af[2][4];
#pragma unroll
            for (int ms = 0; ms < 2; ms++) {
                int r = warp_m * 32 + ms * 16 + (lane & 15);
                int q = (ks >> 3) + (lane >> 4);
                ldm_x4(af[ms], aB + r * 128 + ((q ^ (r & 7)) * 16));
            }
            uint32_t bf[4][4];
#pragma unroll
            for (int np = 0; np < 4; np++) {
                int n = warp_n * 64 + np * 16 + (lane & 7) + ((lane >> 4) << 3);
                int q = (ks >> 3) + ((lane >> 3) & 1);
                ldm_x4(bf[np], bB + n * 128 + ((q ^ (n & 7)) * 16));
            }
#pragma unroll
            for (int ms = 0; ms < 2; ms++)
#pragma unroll
                for (int np = 0; np < 4; np++) {
                    mma_bf16(acc[ms][np * 2 + 0], af[ms], bf[np][0], bf[np][1]);
                    mma_bf16(acc[ms][np * 2 + 1], af[ms], bf[np][2], bf[np][3]);
                }
        }
    };

    load_chunk(0, 0);
    load_chunk(1, 1);
    for (int c = 0; c < HK_NCHUNK; c++) {
        if (c + 1 < HK_NCHUNK) cp_wait<1>(); else cp_wait<0>();
        __syncthreads();
        if (c + 2 < HK_NCHUNK) load_chunk(c + 2, (c + 2) % NSTAGE);
        compute(c % NSTAGE);
    }

#pragma unroll
    for (int ms = 0; ms < 2; ms++) {
#pragma unroll
        for (int half = 0; half < 2; half++) {
            int gr = row0 + warp_m * 32 + ms * 16 + (lane >> 2) + half * 8;
            if (gr >= N_NODES) continue;
#pragma unroll
            for (int np = 0; np < 8; np++) {
                int col = warp_n * 64 + np * 8 + (lane & 3) * 2;
                size_t gi = (size_t)gr * F + col;
                float v0 = acc[ms][np][half * 2 + 0] + s_bias[col];
                float v1 = acc[ms][np][half * 2 + 1] + s_bias[col + 1];
                if (Pin) {
                    float2 pv = *(const float2*)(Pin + gi);
                    v0 += pv.x; v1 += pv.y;
                }
                if (do_relu) { v0 = fmaxf(v0, 0.f); v1 = fmaxf(v1, 0.f); }
                if (write_fp) {
                    *(float2*)(Ofp + gi) = make_float2(v0, v1);
                } else {
                    __nv_bfloat16 h0, l0, h1, l1;
                    split1(v0, h0, l0); split1(v1, h1, l1);
                    __nv_bfloat162 hh; hh.x = h0; hh.y = h1;
                    __nv_bfloat162 ll; ll.x = l0; ll.y = l1;
                    *(__nv_bfloat162*)(Ohi + gi) = hh;
                    *(__nv_bfloat162*)(Olo + gi) = ll;
                }
            }
        }
    }
}

// ---------------- streams / events (created once) ----------------------------
static cudaStream_t g_s2 = nullptr;
static cudaEvent_t  g_ev[4];
struct _StreamInit {
    _StreamInit() {
        cudaStreamCreateWithFlags(&g_s2, cudaStreamNonBlocking);
        for (int i = 0; i < 4; i++)
            cudaEventCreateWithFlags(&g_ev[i], cudaEventDisableTiming);
    }
};
static _StreamInit _stream_init;

// ---------------- launch -----------------------------------------------------
extern "C" void kernel_launch(void* const* d_in, const int* in_sizes, int n_in,
                              void* d_out, int out_size) {
    const float* feat = (const float*)d_in[0];
    const int*   src  = (const int*)d_in[1];
    const int*   dst  = (const int*)d_in[2];
    const float* Wsl[3] = {(const float*)d_in[3], (const float*)d_in[6], (const float*)d_in[9]};
    const float* Wnl[3] = {(const float*)d_in[4], (const float*)d_in[7], (const float*)d_in[10]};
    const float* bl[3]  = {(const float*)d_in[5], (const float*)d_in[8], (const float*)d_in[11]};
    float* out = (float*)d_out;

    __nv_bfloat16 *a0hi, *a0lo, *a1hi, *a1lo, *a2hi, *a2lo, *mhi, *mlo, *wts;
    float* Pbuf;
    cudaGetSymbolAddress((void**)&a0hi, g_a0hi);
    cudaGetSymbolAddress((void**)&a0lo, g_a0lo);
    cudaGetSymbolAddress((void**)&a1hi, g_a1hi);
    cudaGetSymbolAddress((void**)&a1lo, g_a1lo);
    cudaGetSymbolAddress((void**)&a2hi, g_a2hi);
    cudaGetSymbolAddress((void**)&a2lo, g_a2lo);
    cudaGetSymbolAddress((void**)&mhi,  g_mhi);
    cudaGetSymbolAddress((void**)&mlo,  g_mlo);
    cudaGetSymbolAddress((void**)&wts,  g_wts);
    cudaGetSymbolAddress((void**)&Pbuf, g_P);

    const int DSM = NSTAGE * STAGE_BYTES;  // 96KB
    cudaFuncSetAttribute(sage_dual_gemm, cudaFuncAttributeMaxDynamicSharedMemorySize, DSM);
    cudaFuncSetAttribute(sage_half_gemm, cudaFuncAttributeMaxDynamicSharedMemorySize, DSM);

    const int TB = 256;
    const int aggGrid = (N_NODES * 32 + TB - 1) / TB;
    const int gmGrid  = (N_NODES + 127) / 128;
    cudaStream_t s0 = 0, s2 = g_s2;

    // fork s2 off the capture stream
    cudaEventRecord(g_ev[0], s0);
    cudaStreamWaitEvent(s2, g_ev[0], 0);

    // ---- s2: split + weight prep + layer-1 self-GEMM (x@W1s + b1 -> P) ----
    int n4 = N_NODES * F / 4;
    split_kernel<<<(n4 + TB - 1) / TB, TB, 0, s2>>>(feat, a0hi, a0lo, n4);
    prep_w_all_kernel<<<(6 * F * F + TB - 1) / TB, TB, 0, s2>>>(
        Wsl[0], Wnl[0], Wsl[1], Wnl[1], Wsl[2], Wnl[2], wts);
    sage_half_gemm<<<gmGrid, 256, DSM, s2>>>(a0hi, a0lo, wts + 0 * 4 * F * F,
                                             bl[0], nullptr, nullptr, nullptr, Pbuf, 0, 1);
    cudaEventRecord(g_ev[1], s2);

    // ---- s0: CSR build + layer-1 aggregation (fp32 features) ----
    zero_deg_kernel<<<(N_NODES + TB - 1) / TB, TB, 0, s0>>>();
    count_deg_kernel<<<(N_EDGES + TB - 1) / TB, TB, 0, s0>>>(dst);
    assign_start_kernel<<<(N_NODES + TB - 1) / TB, TB, 0, s0>>>();
    fill_edges_kernel<<<(N_EDGES + TB - 1) / TB, TB, 0, s0>>>(src, dst);
    agg_f32_kernel<<<aggGrid, TB, 0, s0>>>(feat);

    // join: layer-1 neigh-GEMM (mean@W1n + P, relu -> a1)
    cudaStreamWaitEvent(s0, g_ev[1], 0);
    sage_half_gemm<<<gmGrid, 256, DSM, s0>>>(mhi, mlo, wts + 0 * 4 * F * F + 2 * F * F,
                                             nullptr, Pbuf, a1hi, a1lo, nullptr, 1, 0);

    // ---- layers 2,3: serial agg + dual-GEMM (R4-proven path) ----
    agg_bf16_kernel<<<aggGrid, TB, 0, s0>>>(a1hi, a1lo);
    sage_dual_gemm<<<gmGrid, 256, DSM, s0>>>(a1hi, a1lo, mhi, mlo, wts + 1 * 4 * F * F,
                                             bl[1], a2hi, a2lo, out, 1, 0);
    agg_bf16_kernel<<<aggGrid, TB, 0, s0>>>(a2hi, a2lo);
    sage_dual_gemm<<<gmGrid, 256, DSM, s0>>>(a2hi, a2lo, mhi, mlo, wts + 2 * 4 * F * F,
                                             bl[2], nullptr, nullptr, out, 0, 1);
}

// round 8
// speedup vs baseline: 1.6468x; 1.0432x over previous
#include <cuda_runtime.h>
#include <cuda_bf16.h>
#include <cstdint>
#include <cstddef>

#define N_NODES 50000
#define N_EDGES 600000
#define F 128

// ---------------- scratch (static device globals) ----------------------------
__device__ int   g_deg[N_NODES];
__device__ int   g_start[N_NODES];
__device__ int   g_pos[N_NODES];
__device__ float g_inv[N_NODES];
__device__ int   g_elist[N_EDGES];
__device__ int   g_total;

__device__ __align__(16) __nv_bfloat16 g_a0hi[N_NODES * F];
__device__ __align__(16) __nv_bfloat16 g_a0lo[N_NODES * F];
__device__ __align__(16) __nv_bfloat16 g_a1hi[N_NODES * F];
__device__ __align__(16) __nv_bfloat16 g_a1lo[N_NODES * F];
__device__ __align__(16) __nv_bfloat16 g_a2hi[N_NODES * F];
__device__ __align__(16) __nv_bfloat16 g_a2lo[N_NODES * F];
__device__ __align__(16) __nv_bfloat16 g_mhi[N_NODES * F];
__device__ __align__(16) __nv_bfloat16 g_mlo[N_NODES * F];
__device__ __align__(16) __nv_bfloat16 g_wts[12 * F * F];  // per layer: Wshi,Wslo,Wnhi,Wnlo

// ---------------- helpers ----------------------------------------------------
__device__ __forceinline__ uint32_t smem_u32(const void* p) {
    uint32_t a;
    asm("{ .reg .u64 t; cvta.to.shared.u64 t, %1; cvt.u32.u64 %0, t; }" : "=r"(a) : "l"(p));
    return a;
}
__device__ __forceinline__ void cp_async16(uint32_t dst, const void* src, uint32_t pbytes) {
    asm volatile("cp.async.cg.shared.global [%0], [%1], 16, %2;"
                 :: "r"(dst), "l"(src), "r"(pbytes));
}
__device__ __forceinline__ void cp_commit() { asm volatile("cp.async.commit_group;"); }
template <int N>
__device__ __forceinline__ void cp_wait() { asm volatile("cp.async.wait_group %0;" :: "n"(N)); }

__device__ __forceinline__ void ldm_x4(uint32_t* r, uint32_t addr) {
    asm volatile("ldmatrix.sync.aligned.m8n8.x4.shared.b16 {%0,%1,%2,%3}, [%4];"
                 : "=r"(r[0]), "=r"(r[1]), "=r"(r[2]), "=r"(r[3]) : "r"(addr));
}
__device__ __forceinline__ void mma_bf16(float* d, const uint32_t* a, uint32_t b0, uint32_t b1) {
    asm volatile("mma.sync.aligned.m16n8k16.row.col.f32.bf16.bf16.f32 "
                 "{%0,%1,%2,%3}, {%4,%5,%6,%7}, {%8,%9}, {%0,%1,%2,%3};"
                 : "+f"(d[0]), "+f"(d[1]), "+f"(d[2]), "+f"(d[3])
                 : "r"(a[0]), "r"(a[1]), "r"(a[2]), "r"(a[3]), "r"(b0), "r"(b1));
}

// ---------------- fp32 -> bf16 hi/lo split -----------------------------------
__device__ __forceinline__ void split1(float v, __nv_bfloat16& h, __nv_bfloat16& l) {
    h = __float2bfloat16_rn(v);
    l = __float2bfloat16_rn(v - __bfloat162float(h));
}

// ---------------- launch 1: zero deg + split features ------------------------
__global__ void fuse_zero_split_kernel(const float* __restrict__ x,
                                       __nv_bfloat16* __restrict__ hi,
                                       __nv_bfloat16* __restrict__ lo) {
    int i = blockIdx.x * blockDim.x + threadIdx.x;
    if (i < N_NODES) g_deg[i] = 0;
    if (i == 0) g_total = 0;
    const int n4 = N_NODES * F / 4;
    if (i < n4) {
        float4 v = ((const float4*)x)[i];
        __align__(8) __nv_bfloat16 h[4], l[4];
        split1(v.x, h[0], l[0]); split1(v.y, h[1], l[1]);
        split1(v.z, h[2], l[2]); split1(v.w, h[3], l[3]);
        ((uint2*)hi)[i] = *(uint2*)h;
        ((uint2*)lo)[i] = *(uint2*)l;
    }
}

// ---------------- launch 2: degree count + weight prep (transpose+split) -----
__global__ void fuse_count_prep_kernel(const int* __restrict__ dst,
                                       const float* __restrict__ W0, const float* __restrict__ W1,
                                       const float* __restrict__ W2, const float* __restrict__ W3,
                                       const float* __restrict__ W4, const float* __restrict__ W5,
                                       __nv_bfloat16* __restrict__ wts) {
    int i = blockIdx.x * blockDim.x + threadIdx.x;
    if (i < N_EDGES) atomicAdd(&g_deg[dst[i]], 1);
    if (i < 6 * F * F) {
        int w = i / (F * F), r = i % (F * F);
        int n = r >> 7, k = r & 127;
        const float* Wp[6] = {W0, W1, W2, W3, W4, W5};
        float v = Wp[w][k * F + n];
        __nv_bfloat16 h, l;
        split1(v, h, l);
        int layer = w >> 1, sn = w & 1;
        size_t base = ((size_t)layer * 4 + sn * 2) * F * F;
        wts[base + r]         = h;
        wts[base + F * F + r] = l;
    }
}

// ---------------- launches 3,4: CSR finalize ---------------------------------
__global__ void assign_start_kernel() {
    int i = blockIdx.x * blockDim.x + threadIdx.x;
    if (i >= N_NODES) return;
    int d = g_deg[i];
    int s = atomicAdd(&g_total, d);
    g_start[i] = s;
    g_pos[i]   = s;
    g_inv[i]   = 1.0f / fmaxf((float)d, 1.0f);
}
__global__ void fill_edges_kernel(const int* __restrict__ src, const int* __restrict__ dst) {
    int e = blockIdx.x * blockDim.x + threadIdx.x;
    if (e < N_EDGES) {
        int p = atomicAdd(&g_pos[dst[e]], 1);
        g_elist[p] = src[e];
    }
}

// ---------------- mean aggregation (warp per node) ---------------------------
__global__ void agg_f32_kernel(const float* __restrict__ x) {
    int w    = (blockIdx.x * blockDim.x + threadIdx.x) >> 5;
    int lane = threadIdx.x & 31;
    if (w >= N_NODES) return;
    int s0 = g_start[w];
    int d  = g_deg[w];
    int co = lane * 4;
    float a0 = 0.f, a1 = 0.f, a2 = 0.f, a3 = 0.f;
    for (int j = 0; j < d; j++) {
        int s = g_elist[s0 + j];
        float4 v = *(const float4*)(x + (size_t)s * F + co);
        a0 += v.x; a1 += v.y; a2 += v.z; a3 += v.w;
    }
    float iv = g_inv[w];
    __align__(8) __nv_bfloat16 h[4], l[4];
    split1(a0 * iv, h[0], l[0]); split1(a1 * iv, h[1], l[1]);
    split1(a2 * iv, h[2], l[2]); split1(a3 * iv, h[3], l[3]);
    *(uint2*)(g_mhi + (size_t)w * F + co) = *(uint2*)h;
    *(uint2*)(g_mlo + (size_t)w * F + co) = *(uint2*)l;
}

__global__ void agg_bf16_kernel(const __nv_bfloat16* __restrict__ xhi,
                                const __nv_bfloat16* __restrict__ xlo) {
    int w    = (blockIdx.x * blockDim.x + threadIdx.x) >> 5;
    int lane = threadIdx.x & 31;
    if (w >= N_NODES) return;
    int s0 = g_start[w];
    int d  = g_deg[w];
    int co = lane * 4;
    float a0 = 0.f, a1 = 0.f, a2 = 0.f, a3 = 0.f;
    for (int j = 0; j < d; j++) {
        int s = g_elist[s0 + j];
        uint2 uh = *(const uint2*)(xhi + (size_t)s * F + co);
        uint2 ul = *(const uint2*)(xlo + (size_t)s * F + co);
        float2 h0 = __bfloat1622float2(*(__nv_bfloat162*)&uh.x);
        float2 h1 = __bfloat1622float2(*(__nv_bfloat162*)&uh.y);
        float2 l0 = __bfloat1622float2(*(__nv_bfloat162*)&ul.x);
        float2 l1 = __bfloat1622float2(*(__nv_bfloat162*)&ul.y);
        a0 += h0.x + l0.x; a1 += h0.y + l0.y;
        a2 += h1.x + l1.x; a3 += h1.y + l1.y;
    }
    float iv = g_inv[w];
    __align__(8) __nv_bfloat16 h[4], l[4];
    split1(a0 * iv, h[0], l[0]); split1(a1 * iv, h[1], l[1]);
    split1(a2 * iv, h[2], l[2]); split1(a3 * iv, h[3], l[3]);
    *(uint2*)(g_mhi + (size_t)w * F + co) = *(uint2*)h;
    *(uint2*)(g_mlo + (size_t)w * F + co) = *(uint2*)l;
}

// ---------------- dual-GEMM (R4-proven, unchanged) ---------------------------
#define STAGE_BYTES 32768
#define NSTAGE 3
#define DK_NCHUNK 12
__global__ void __launch_bounds__(256, 2)
sage_dual_gemm(const __nv_bfloat16* __restrict__ Ahi,
               const __nv_bfloat16* __restrict__ Alo,
               const __nv_bfloat16* __restrict__ Mhi,
               const __nv_bfloat16* __restrict__ Mlo,
               const __nv_bfloat16* __restrict__ Wb,   // Wshi,Wslo,Wnhi,Wnlo ([n][k])
               const float* __restrict__ bias,
               __nv_bfloat16* __restrict__ Ohi,
               __nv_bfloat16* __restrict__ Olo,
               float* __restrict__ Ofp,
               int do_relu, int write_fp) {
    extern __shared__ __align__(16) char sm[];
    __shared__ float s_bias[F];

    int tid = threadIdx.x, lane = tid & 31, wid = tid >> 5;
    int warp_m = wid & 3, warp_n = wid >> 2;
    int row0 = blockIdx.x * 128;

    if (tid < F) s_bias[tid] = bias[tid];

    const __nv_bfloat16* Aptr[4] = {Ahi, Alo, Mhi, Mlo};
    const int AI[6] = {0, 0, 1, 2, 2, 3};
    const int BI[6] = {0, 1, 0, 2, 3, 2};
    uint32_t smb = smem_u32(sm);

    float acc[2][8][4];
#pragma unroll
    for (int i = 0; i < 2; i++)
#pragma unroll
        for (int j = 0; j < 8; j++)
#pragma unroll
            for (int k = 0; k < 4; k++) acc[i][j][k] = 0.f;

    auto load_chunk = [&](int c, int stg) {
        int seg = c >> 1;
        int kc  = (c & 1) * 64;
        const __nv_bfloat16* Ag = Aptr[AI[seg]];
        const __nv_bfloat16* Bg = Wb + (size_t)BI[seg] * F * F;
        uint32_t aB = smb + stg * STAGE_BYTES;
        uint32_t bB = aB + 16384;
#pragma unroll
        for (int i = 0; i < 4; i++) {
            int idx = tid + i * 256;
            int row = idx >> 3, q = idx & 7;
            uint32_t sw = (uint32_t)(row * 128 + ((q ^ (row & 7)) * 16));
            int gr = row0 + row;
            int grc = (gr < N_NODES) ? gr : 0;
            uint32_t p = (gr < N_NODES) ? 16u : 0u;
            cp_async16(aB + sw, Ag + (size_t)grc * F + kc + q * 8, p);
            cp_async16(bB + sw, Bg + (size_t)row * F + kc + q * 8, 16u);
        }
        cp_commit();
    };

    auto compute = [&](int stg) {
        uint32_t aB = smb + stg * STAGE_BYTES;
        uint32_t bB = aB + 16384;
#pragma unroll
        for (int ks = 0; ks < 64; ks += 16) {
            uint32_t af[2][4];
#pragma unroll
            for (int ms = 0; ms < 2; ms++) {
                int r = warp_m * 32 + ms * 16 + (lane & 15);
                int q = (ks >> 3) + (lane >> 4);
                ldm_x4(af[ms], aB + r * 128 + ((q ^ (r & 7)) * 16));
            }
            uint32_t bf[4][4];
#pragma unroll
            for (int np = 0; np < 4; np++) {
                int n = warp_n * 64 + np * 16 + (lane & 7) + ((lane >> 4) << 3);
                int q = (ks >> 3) + ((lane >> 3) & 1);
                ldm_x4(bf[np], bB + n * 128 + ((q ^ (n & 7)) * 16));
            }
#pragma unroll
            for (int ms = 0; ms < 2; ms++)
#pragma unroll
                for (int np = 0; np < 4; np++) {
                    mma_bf16(acc[ms][np * 2 + 0], af[ms], bf[np][0], bf[np][1]);
                    mma_bf16(acc[ms][np * 2 + 1], af[ms], bf[np][2], bf[np][3]);
                }
        }
    };

    load_chunk(0, 0);
    load_chunk(1, 1);
    for (int c = 0; c < DK_NCHUNK; c++) {
        if (c + 1 < DK_NCHUNK) cp_wait<1>(); else cp_wait<0>();
        __syncthreads();
        if (c + 2 < DK_NCHUNK) load_chunk(c + 2, (c + 2) % NSTAGE);
        compute(c % NSTAGE);
    }

#pragma unroll
    for (int ms = 0; ms < 2; ms++) {
#pragma unroll
        for (int half = 0; half < 2; half++) {
            int gr = row0 + warp_m * 32 + ms * 16 + (lane >> 2) + half * 8;
            if (gr >= N_NODES) continue;
#pragma unroll
            for (int np = 0; np < 8; np++) {
                int col = warp_n * 64 + np * 8 + (lane & 3) * 2;
                float v0 = acc[ms][np][half * 2 + 0] + s_bias[col];
                float v1 = acc[ms][np][half * 2 + 1] + s_bias[col + 1];
                if (do_relu) { v0 = fmaxf(v0, 0.f); v1 = fmaxf(v1, 0.f); }
                size_t gi = (size_t)gr * F + col;
                if (write_fp) {
                    *(float2*)(Ofp + gi) = make_float2(v0, v1);
                } else {
                    __nv_bfloat16 h0, l0, h1, l1;
                    split1(v0, h0, l0); split1(v1, h1, l1);
                    __nv_bfloat162 hh; hh.x = h0; hh.y = h1;
                    __nv_bfloat162 ll; ll.x = l0; ll.y = l1;
                    *(__nv_bfloat162*)(Ohi + gi) = hh;
                    *(__nv_bfloat162*)(Olo + gi) = ll;
                }
            }
        }
    }
}

// ---------------- launch -----------------------------------------------------
extern "C" void kernel_launch(void* const* d_in, const int* in_sizes, int n_in,
                              void* d_out, int out_size) {
    const float* feat = (const float*)d_in[0];
    const int*   src  = (const int*)d_in[1];
    const int*   dst  = (const int*)d_in[2];
    const float* Wsl[3] = {(const float*)d_in[3], (const float*)d_in[6], (const float*)d_in[9]};
    const float* Wnl[3] = {(const float*)d_in[4], (const float*)d_in[7], (const float*)d_in[10]};
    const float* bl[3]  = {(const float*)d_in[5], (const float*)d_in[8], (const float*)d_in[11]};
    float* out = (float*)d_out;

    __nv_bfloat16 *a0hi, *a0lo, *a1hi, *a1lo, *a2hi, *a2lo, *mhi, *mlo, *wts;
    cudaGetSymbolAddress((void**)&a0hi, g_a0hi);
    cudaGetSymbolAddress((void**)&a0lo, g_a0lo);
    cudaGetSymbolAddress((void**)&a1hi, g_a1hi);
    cudaGetSymbolAddress((void**)&a1lo, g_a1lo);
    cudaGetSymbolAddress((void**)&a2hi, g_a2hi);
    cudaGetSymbolAddress((void**)&a2lo, g_a2lo);
    cudaGetSymbolAddress((void**)&mhi,  g_mhi);
    cudaGetSymbolAddress((void**)&mlo,  g_mlo);
    cudaGetSymbolAddress((void**)&wts,  g_wts);

    const int DSM = NSTAGE * STAGE_BYTES;  // 96KB
    cudaFuncSetAttribute(sage_dual_gemm, cudaFuncAttributeMaxDynamicSharedMemorySize, DSM);

    const int TB = 256;
    const int aggGrid = (N_NODES * 32 + TB - 1) / TB;
    const int gmGrid  = (N_NODES + 127) / 128;
    const int n4 = N_NODES * F / 4;

    // launches 1-5 (exactly; dual1 is launch #6 -> ncu -s 5 -c 1 profiles it)
    fuse_zero_split_kernel<<<(n4 + TB - 1) / TB, TB>>>(feat, a0hi, a0lo);
    fuse_count_prep_kernel<<<(N_EDGES + TB - 1) / TB, TB>>>(
        dst, Wsl[0], Wnl[0], Wsl[1], Wnl[1], Wsl[2], Wnl[2], wts);
    assign_start_kernel<<<(N_NODES + TB - 1) / TB, TB>>>();
    fill_edges_kernel<<<(N_EDGES + TB - 1) / TB, TB>>>(src, dst);
    agg_f32_kernel<<<aggGrid, TB>>>(feat);

    // layer 1 (launch #6 — profiled)
    sage_dual_gemm<<<gmGrid, 256, DSM>>>(a0hi, a0lo, mhi, mlo, wts + 0 * 4 * F * F,
                                         bl[0], a1hi, a1lo, out, 1, 0);
    // layer 2
    agg_bf16_kernel<<<aggGrid, TB>>>(a1hi, a1lo);
    sage_dual_gemm<<<gmGrid, 256, DSM>>>(a1hi, a1lo, mhi, mlo, wts + 1 * 4 * F * F,
                                         bl[1], a2hi, a2lo, out, 1, 0);
    // layer 3
    agg_bf16_kernel<<<aggGrid, TB>>>(a2hi, a2lo);
    sage_dual_gemm<<<gmGrid, 256, DSM>>>(a2hi, a2lo, mhi, mlo, wts + 2 * 4 * F * F,
                                         bl[2], nullptr, nullptr, out, 0, 1);
}